// round 8
// baseline (speedup 1.0000x reference)
#include <cuda_runtime.h>
#include <cstdint>

#define SEQ    8192
#define NH     32
#define NKV    8
#define NHT    (NH + NKV)           // 40
#define HD     128
#define HALF   64
#define QSIZE  (NH * HD)            // 4096
#define KVSIZE (NKV * HD)           // 1024
#define ROW    (QSIZE + 2 * KVSIZE) // 6144 floats = 24576 B
#define ROW_BYTES (ROW * 4)
#define EPSV   1e-6f

#define THREADS 256                 // 8 warps, 5 heads per warp

__device__ __forceinline__ uint32_t smem_u32(const void* p) {
    return (uint32_t)__cvta_generic_to_shared(p);
}

__global__ __launch_bounds__(THREADS)
void qknorm_rope_kernel(const float* __restrict__ qkv,
                        const float* __restrict__ qw,
                        const float* __restrict__ kw,
                        const float* __restrict__ cosw,
                        const float* __restrict__ sinw,
                        float* __restrict__ out)
{
    __shared__ __align__(128) float s_in[ROW];     // 24 KB: q|k|v for one token
    __shared__ __align__(8) unsigned long long s_mbar;

    const int tid  = threadIdx.x;
    const int s    = blockIdx.x;                   // token index
    const uint32_t mbar = smem_u32(&s_mbar);
    const uint32_t sin_addr = smem_u32(s_in);

    if (tid == 0) {
        asm volatile("mbarrier.init.shared::cta.b64 [%0], %1;"
                     :: "r"(mbar), "r"(1));
    }
    __syncthreads();

    if (tid == 0) {
        asm volatile("mbarrier.arrive.expect_tx.shared::cta.b64 _, [%0], %1;"
                     :: "r"(mbar), "r"((uint32_t)ROW_BYTES));
        const float* gsrc = qkv + (size_t)s * ROW;
        asm volatile(
            "cp.async.bulk.shared::cta.global.mbarrier::complete_tx::bytes "
            "[%0], [%1], %2, [%3];"
            :: "r"(sin_addr), "l"(gsrc), "r"((uint32_t)ROW_BYTES), "r"(mbar)
            : "memory");
    }

    // All threads wait for the bulk load (phase 0), acquire semantics.
    {
        uint32_t done;
        asm volatile(
            "{\n\t.reg .pred p;\n\t"
            "mbarrier.try_wait.parity.acquire.cta.shared::cta.b64 p, [%1], %2, 0x989680;\n\t"
            "selp.b32 %0, 1, 0, p;\n\t}"
            : "=r"(done) : "r"(mbar), "r"(0u) : "memory");
        while (!done) {
            asm volatile(
                "{\n\t.reg .pred p;\n\t"
                "mbarrier.try_wait.parity.acquire.cta.shared::cta.b64 p, [%1], %2, 0x989680;\n\t"
                "selp.b32 %0, 1, 0, p;\n\t}"
                : "=r"(done) : "r"(mbar), "r"(0u) : "memory");
        }
    }

    // V passthrough: bulk store straight from smem (no transform, no registers).
    if (tid == 0) {
        float* vdst = out + (size_t)SEQ * (QSIZE + KVSIZE) + (size_t)s * KVSIZE;
        asm volatile(
            "cp.async.bulk.global.shared::cta.bulk_group [%0], [%1], %2;"
            :: "l"(vdst), "r"(sin_addr + (QSIZE + KVSIZE) * 4),
               "r"((uint32_t)(KVSIZE * 4))
            : "memory");
        asm volatile("cp.async.bulk.commit_group;" ::: "memory");
    }

    // Q/K: 8 warps x 5 heads. Per head: full 32-lane layout, each lane owns
    // the rotate_half pair (c, c+64) with c = lane*2 (float2 granularity).
    const int warp = tid >> 5;
    const int lane = tid & 31;
    const int c    = lane * 2;

    // Column-only constants: hoisted once per lane.
    const float2 clo = *reinterpret_cast<const float2*>(cosw + c);
    const float2 chi = *reinterpret_cast<const float2*>(cosw + c + HALF);
    const float2 slo = *reinterpret_cast<const float2*>(sinw + c);
    const float2 shi = *reinterpret_cast<const float2*>(sinw + c + HALF);
    const float2 wql = *reinterpret_cast<const float2*>(qw + c);
    const float2 wqh = *reinterpret_cast<const float2*>(qw + c + HALF);
    const float2 wkl = *reinterpret_cast<const float2*>(kw + c);
    const float2 wkh = *reinterpret_cast<const float2*>(kw + c + HALF);

    #pragma unroll
    for (int i = 0; i < 5; i++) {
        const int h = warp * 5 + i;                // 0..39
        const float* hs = s_in + h * HD;

        float2 xlo = *reinterpret_cast<const float2*>(hs + c);
        float2 xhi = *reinterpret_cast<const float2*>(hs + c + HALF);

        float ss = xlo.x * xlo.x + xlo.y * xlo.y
                 + xhi.x * xhi.x + xhi.y * xhi.y;
        #pragma unroll
        for (int off = 16; off > 0; off >>= 1)
            ss += __shfl_xor_sync(0xffffffffu, ss, off);

        const float inv = rsqrtf(ss * (1.0f / HD) + EPSV);

        const bool isq = (h < NH);
        const float2 wl = isq ? wql : wkl;
        const float2 wh = isq ? wqh : wkh;
        float* dst = isq ? (out + (size_t)s * QSIZE + h * HD)
                         : (out + (size_t)SEQ * QSIZE + (size_t)s * KVSIZE
                                + (h - NH) * HD);

        const float nl0 = xlo.x * inv * wl.x, nl1 = xlo.y * inv * wl.y;
        const float nh0 = xhi.x * inv * wh.x, nh1 = xhi.y * inv * wh.y;

        float2 olo, ohi;
        olo.x = nl0 * clo.x - nh0 * slo.x;
        olo.y = nl1 * clo.y - nh1 * slo.y;
        ohi.x = nh0 * chi.x + nl0 * shi.x;
        ohi.y = nh1 * chi.y + nl1 * shi.y;

        __stcs(reinterpret_cast<float2*>(dst + c), olo);
        __stcs(reinterpret_cast<float2*>(dst + c + HALF), ohi);
    }

    // Keep smem alive until the V bulk store has finished reading it.
    if (tid == 0) {
        asm volatile("cp.async.bulk.wait_group 0;" ::: "memory");
    }
    __syncthreads();
}

extern "C" void kernel_launch(void* const* d_in, const int* in_sizes, int n_in,
                              void* d_out, int out_size)
{
    const float* qkv  = (const float*)d_in[0];
    const float* qw   = (const float*)d_in[1];
    const float* kw   = (const float*)d_in[2];
    const float* cosw = (const float*)d_in[3];
    const float* sinw = (const float*)d_in[4];
    float* out = (float*)d_out;

    qknorm_rope_kernel<<<SEQ, THREADS>>>(qkv, qw, kw, cosw, sinw, out);
}